// round 2
// baseline (speedup 1.0000x reference)
#include <cuda_runtime.h>
#include <cuda_bf16.h>
#include <math.h>

#define T_STEPS     2048
#define IN_SIZE     2048
#define HID_SIZE    4096
#define OUT_SIZE    2048
#define MAX_SM      148

// ---------------- device scratch (allocation-free) ----------------
__device__ __align__(16) float g_Z[(size_t)T_STEPS * HID_SIZE];   // 32 MB: Z = x@Wx^T + bh
__device__ __align__(16) float g_y[OUT_SIZE];
__device__ __align__(16) float g_h[HID_SIZE];
__device__ unsigned g_bar_count = 0;
__device__ volatile unsigned g_bar_gen = 0;

// ---------------- grid barrier (sense-reversing, atomic) ----------------
__device__ __forceinline__ void grid_barrier(int nblocks) {
    __syncthreads();
    if (threadIdx.x == 0) {
        __threadfence();
        unsigned gen = g_bar_gen;
        if (atomicAdd(&g_bar_count, 1u) == (unsigned)nblocks - 1u) {
            g_bar_count = 0;
            __threadfence();
            g_bar_gen = gen + 1u;
        } else {
            while (g_bar_gen == gen) { }
            __threadfence();
        }
    }
    __syncthreads();
}

// ---------------- GEMM: Z[t][j] = sum_i x[t][i]*Wx[j][i] + bh[j] ----------------
// A = x [M=2048][K=2048] rm, B = Wx [N=4096][K=2048] rm (NT gemm), C = g_Z [M][N]
#define GM_BM 64
#define GM_BN 64
#define GM_BK 32

__global__ __launch_bounds__(256) void gemm_z_kernel(
    const float* __restrict__ A,
    const float* __restrict__ B,
    const float* __restrict__ bh)
{
    __shared__ __align__(16) float As[GM_BK][GM_BM + 4];
    __shared__ __align__(16) float Bs[GM_BK][GM_BN + 4];

    const int tid = threadIdx.x;
    const int tx  = tid & 15;       // 0..15
    const int ty  = tid >> 4;       // 0..15
    const int m0  = blockIdx.y * GM_BM;
    const int n0  = blockIdx.x * GM_BN;
    const int K   = IN_SIZE;
    const int N   = HID_SIZE;

    float acc[4][4] = {};

    for (int k0 = 0; k0 < K; k0 += GM_BK) {
        #pragma unroll
        for (int l = 0; l < 2; ++l) {
            int idx = tid + l * 256;       // 0..511
            int r   = idx >> 3;            // row in tile 0..63
            int c4  = idx & 7;             // float4 col 0..7
            float4 va = *(const float4*)(A + (size_t)(m0 + r) * K + k0 + c4 * 4);
            As[c4 * 4 + 0][r] = va.x;
            As[c4 * 4 + 1][r] = va.y;
            As[c4 * 4 + 2][r] = va.z;
            As[c4 * 4 + 3][r] = va.w;
            float4 vb = *(const float4*)(B + (size_t)(n0 + r) * K + k0 + c4 * 4);
            Bs[c4 * 4 + 0][r] = vb.x;
            Bs[c4 * 4 + 1][r] = vb.y;
            Bs[c4 * 4 + 2][r] = vb.z;
            Bs[c4 * 4 + 3][r] = vb.w;
        }
        __syncthreads();

        #pragma unroll
        for (int kk = 0; kk < GM_BK; ++kk) {
            float4 a4 = *(const float4*)&As[kk][ty * 4];
            float4 b4 = *(const float4*)&Bs[kk][tx * 4];
            float a[4] = {a4.x, a4.y, a4.z, a4.w};
            float b[4] = {b4.x, b4.y, b4.z, b4.w};
            #pragma unroll
            for (int i = 0; i < 4; ++i)
                #pragma unroll
                for (int j = 0; j < 4; ++j)
                    acc[i][j] += a[i] * b[j];
        }
        __syncthreads();
    }

    float4 bias = *(const float4*)(bh + n0 + tx * 4);
    #pragma unroll
    for (int i = 0; i < 4; ++i) {
        float4 o;
        o.x = acc[i][0] + bias.x;
        o.y = acc[i][1] + bias.y;
        o.z = acc[i][2] + bias.z;
        o.w = acc[i][3] + bias.w;
        *(float4*)(g_Z + (size_t)(m0 + ty * 4 + i) * N + n0 + tx * 4) = o;
    }
}

// ---------------- persistent recurrent kernel ----------------
// phase1: h[j] = tanh(Z[t][j] + Wh[j,:] . y_prev)        (4096 rows, dot len 2048)
// phase2: y[i] = by[i] + Wy[i,:] . h                     (2048 rows, dot len 4096)
__global__ __launch_bounds__(1024, 1) void rnn_kernel(
    const float* __restrict__ Wh,
    const float* __restrict__ Wy,
    const float* __restrict__ by,
    float* __restrict__ out,
    int nblocks)
{
    __shared__ __align__(16) float s_vec[HID_SIZE];   // holds y (2048) or h (4096)
    __shared__ float s_part[16];

    const int tid  = threadIdx.x;
    const int warp = tid >> 5;
    const int lane = tid & 31;
    const int bid  = blockIdx.x;

    // row ranges owned by this CTA (fixed across all steps -> L1 locality for Wh)
    const int j0 = (bid * HID_SIZE) / nblocks;
    const int j1 = ((bid + 1) * HID_SIZE) / nblocks;
    const int i0 = (bid * OUT_SIZE) / nblocks;
    const int i1 = ((bid + 1) * OUT_SIZE) / nblocks;

    // init y_0 = 0 (every replay)
    for (int i = bid * blockDim.x + tid; i < OUT_SIZE; i += nblocks * blockDim.x)
        g_y[i] = 0.0f;
    grid_barrier(nblocks);

    for (int t = 0; t < T_STEPS; ++t) {
        // ---- stage y_prev into smem (L2-coherent read) ----
        {
            float4* sv = (float4*)s_vec;
            const float4* gy = (const float4*)g_y;
            for (int c = tid; c < OUT_SIZE / 4; c += blockDim.x)
                sv[c] = __ldcg(gy + c);
        }
        __syncthreads();

        // ---- phase 1: hidden rows (one row per warp; Wh via L1) ----
        {
            const int row = j0 + warp;
            if (row < j1) {
                const float4* wrow = (const float4*)(Wh + (size_t)row * OUT_SIZE);
                const float4* yv   = (const float4*)s_vec;
                float ax = 0.f, ay = 0.f, az = 0.f, aw = 0.f;
                #pragma unroll
                for (int c = lane; c < OUT_SIZE / 4; c += 32) {
                    float4 w4 = wrow[c];
                    float4 v4 = yv[c];
                    ax += w4.x * v4.x;
                    ay += w4.y * v4.y;
                    az += w4.z * v4.z;
                    aw += w4.w * v4.w;
                }
                float acc = (ax + ay) + (az + aw);
                #pragma unroll
                for (int o = 16; o; o >>= 1)
                    acc += __shfl_xor_sync(0xFFFFFFFFu, acc, o);
                if (lane == 0) {
                    float z = __ldcg(g_Z + (size_t)t * HID_SIZE + row);
                    __stcg(g_h + row, tanhf(acc + z));
                }
            }
        }
        grid_barrier(nblocks);

        // ---- stage h into smem ----
        {
            float4* sv = (float4*)s_vec;
            const float4* gh = (const float4*)g_h;
            for (int c = tid; c < HID_SIZE / 4; c += blockDim.x)
                sv[c] = __ldcg(gh + c);
        }
        __syncthreads();

        // ---- phase 2: output rows (one row per warp-pair; Wy via L2 stream) ----
        {
            const int pair = warp >> 1;
            const int half = warp & 1;
            const int row  = i0 + pair;
            float acc = 0.f;
            if (row < i1) {
                const float4* wrow = (const float4*)(Wy + (size_t)row * HID_SIZE) + half * 512;
                const float4* hv   = (const float4*)s_vec + half * 512;
                float ax = 0.f, ay = 0.f, az = 0.f, aw = 0.f;
                #pragma unroll
                for (int c = lane; c < 512; c += 32) {
                    float4 w4 = __ldcg(wrow + c);
                    float4 v4 = hv[c];
                    ax += w4.x * v4.x;
                    ay += w4.y * v4.y;
                    az += w4.z * v4.z;
                    aw += w4.w * v4.w;
                }
                acc = (ax + ay) + (az + aw);
                #pragma unroll
                for (int o = 16; o; o >>= 1)
                    acc += __shfl_xor_sync(0xFFFFFFFFu, acc, o);
            }
            if (half == 1 && lane == 0)
                s_part[pair] = acc;
            __syncthreads();
            if (half == 0 && lane == 0 && row < i1) {
                float v = acc + s_part[pair] + by[row];
                __stcg(g_y + row, v);
                out[(size_t)t * OUT_SIZE + row] = v;
            }
        }
        grid_barrier(nblocks);
    }
}

// ---------------- launch ----------------
extern "C" void kernel_launch(void* const* d_in, const int* in_sizes, int n_in,
                              void* d_out, int out_size)
{
    const float* x  = (const float*)d_in[0];
    const float* Wx = (const float*)d_in[1];
    const float* Wh = (const float*)d_in[2];
    const float* Wy = (const float*)d_in[3];
    const float* bh = (const float*)d_in[4];
    const float* by = (const float*)d_in[5];
    float* out = (float*)d_out;

    int nsm = MAX_SM;
    if (cudaDeviceGetAttribute(&nsm, cudaDevAttrMultiProcessorCount, 0) != cudaSuccess)
        nsm = MAX_SM;
    if (nsm > MAX_SM || nsm <= 0) nsm = MAX_SM;

    // 1) Z = x @ Wx^T + bh  (parallel GEMM)
    dim3 gg(HID_SIZE / GM_BN, T_STEPS / GM_BM);
    gemm_z_kernel<<<gg, 256>>>(x, Wx, bh);

    // 2) sequential recurrence (persistent kernel, custom grid barrier)
    rnn_kernel<<<nsm, 1024>>>(Wh, Wy, by, out, nsm);
}